// round 7
// baseline (speedup 1.0000x reference)
#include <cuda_runtime.h>
#include <cuda_bf16.h>
#include <math.h>
#include <stdint.h>

// Problem constants
#define B_  4
#define N_  4096
#define F_  256
#define U_  128
#define M_  (B_ * N_)          // 16384 rows of f
#define MAXNZ 192

// ---------------- device scratch (no allocations allowed) ----------------
__device__ float g_f  [M_ * U_];        // f = inputs @ w   [B*N, U]   (8 MB)
__device__ float g_aiT[N_ * U_];        // ai^T [N, U]                 (2 MB)
__device__ float g_ajT[N_ * U_];        // aj^T [N, U]                 (2 MB)
__device__ int   g_rows[N_ * MAXNZ];    // per-column neighbor lists   (3 MB)
__device__ int   g_cnt [N_];

// ---------------- f32x2 packed-FMA helpers ----------------
__device__ __forceinline__ unsigned long long pk2(float x, float y) {
    unsigned long long r;
    asm("mov.b64 %0, {%1,%2};" : "=l"(r) : "f"(x), "f"(y));
    return r;
}
__device__ __forceinline__ void upk2(unsigned long long v, float& x, float& y) {
    asm("mov.b64 {%0,%1}, %2;" : "=f"(x), "=f"(y) : "l"(v));
}
__device__ __forceinline__ void ffma2(unsigned long long& d, unsigned long long a,
                                      unsigned long long b) {
    asm("fma.rn.f32x2 %0, %1, %2, %0;" : "+l"(d) : "l"(a), "l"(b));
}

// ---------------- kernel 1: transpose ai, aj  ([U,N] -> [N,U]) ----------------
__global__ void transpose_k(const float* __restrict__ ai, const float* __restrict__ aj) {
    __shared__ float tile[32][33];
    const float* src = blockIdx.z ? aj : ai;
    float* dst       = blockIdx.z ? g_ajT : g_aiT;
    int n0 = blockIdx.x * 32;
    int u0 = blockIdx.y * 32;
    int tx = threadIdx.x, ty = threadIdx.y;
#pragma unroll
    for (int r = 0; r < 32; r += 8)
        tile[ty + r][tx] = src[(size_t)(u0 + ty + r) * N_ + n0 + tx];
    __syncthreads();
#pragma unroll
    for (int r = 0; r < 32; r += 8)
        dst[(size_t)(n0 + ty + r) * U_ + u0 + tx] = tile[tx][ty + r];
}

// ---------------- kernel 2: f = inputs @ w  (16384x256 @ 256x128, fp32/f32x2) ----
// BM=128, BN=128, BK=32; 256 threads; 8x8 micro-tile per thread.
__global__ __launch_bounds__(256) void gemm_f(const float* __restrict__ A,
                                              const float* __restrict__ W) {
    __shared__ float As[32][132];   // [BK][BM+4], transposed A tile
    __shared__ float Bs[32][128];   // [BK][BN]
    const int tid = threadIdx.x;
    const int m0  = blockIdx.x * 128;
    const int tm  = (tid >> 4) << 3;   // 0..120 step 8
    const int tn  = (tid & 15) << 3;   // 0..120 step 8

    unsigned long long acc[8][4];
#pragma unroll
    for (int i = 0; i < 8; i++)
#pragma unroll
        for (int j = 0; j < 4; j++) acc[i][j] = 0ull;

    for (int k0 = 0; k0 < F_; k0 += 32) {
        // load A tile (128x32) -> As transposed
#pragma unroll
        for (int r = 0; r < 4; r++) {
            int idx = tid + 256 * r;             // 0..1023 float4s
            int row = idx >> 3;                  // 0..127
            int c4  = idx & 7;                   // 0..7
            float4 v = *(const float4*)(A + (size_t)(m0 + row) * F_ + k0 + c4 * 4);
            As[c4 * 4 + 0][row] = v.x;
            As[c4 * 4 + 1][row] = v.y;
            As[c4 * 4 + 2][row] = v.z;
            As[c4 * 4 + 3][row] = v.w;
        }
        // load W tile (32x128)
#pragma unroll
        for (int r = 0; r < 4; r++) {
            int idx = tid + 256 * r;
            int row = idx >> 5;                  // 0..31
            int c4  = idx & 31;                  // 0..31
            *(float4*)&Bs[row][c4 * 4] =
                *(const float4*)(W + (size_t)(k0 + row) * U_ + c4 * 4);
        }
        __syncthreads();
#pragma unroll
        for (int kk = 0; kk < 32; kk++) {
            float a[8];
            *(float4*)&a[0] = *(const float4*)&As[kk][tm];
            *(float4*)&a[4] = *(const float4*)&As[kk][tm + 4];
            ulonglong2 b01 = *(const ulonglong2*)&Bs[kk][tn];
            ulonglong2 b23 = *(const ulonglong2*)&Bs[kk][tn + 4];
            unsigned long long b[4] = {b01.x, b01.y, b23.x, b23.y};
#pragma unroll
            for (int i = 0; i < 8; i++) {
                unsigned long long ar = pk2(a[i], a[i]);
#pragma unroll
                for (int j = 0; j < 4; j++) ffma2(acc[i][j], ar, b[j]);
            }
        }
        __syncthreads();
    }
    // store
#pragma unroll
    for (int i = 0; i < 8; i++) {
        float x0, x1, x2, x3, x4, x5, x6, x7;
        upk2(acc[i][0], x0, x1);
        upk2(acc[i][1], x2, x3);
        upk2(acc[i][2], x4, x5);
        upk2(acc[i][3], x6, x7);
        float* cp = g_f + (size_t)(m0 + tm + i) * U_ + tn;
        *(float4*)cp       = make_float4(x0, x1, x2, x3);
        *(float4*)(cp + 4) = make_float4(x4, x5, x6, x7);
    }
}

// ---------------- kernel 3: build per-column neighbor lists (deterministic) -----
// adj is symmetric, so column j == row j -> coalesced row scan.
// Entry encoding: i | (0x10000 if this is the diagonal AND adj[j,j]>0  -> mask==2)
__global__ __launch_bounds__(128) void build_k(const float* __restrict__ adj) {
    const int j = blockIdx.x;
    const int t = threadIdx.x;
    __shared__ int sc[128];
    const float* row = adj + (size_t)j * N_;

    int cnt = 0;
#pragma unroll
    for (int k = 0; k < 32; k++) {
        int i = k * 128 + t;
        float v = row[i];
        if (i == j || v > 0.0f) cnt++;
    }
    sc[t] = cnt;
    __syncthreads();
    // inclusive scan (Hillis-Steele)
    for (int off = 1; off < 128; off <<= 1) {
        int add = (t >= off) ? sc[t - off] : 0;
        __syncthreads();
        sc[t] += add;
        __syncthreads();
    }
    int pos = sc[t] - cnt;
    int* dst = g_rows + (size_t)j * MAXNZ;
#pragma unroll
    for (int k = 0; k < 32; k++) {
        int i = k * 128 + t;
        float v = row[i];
        if (i == j) {
            if (pos < MAXNZ) dst[pos] = i | ((v > 0.0f) ? 0x10000 : 0);
            pos++;
        } else if (v > 0.0f) {
            if (pos < MAXNZ) dst[pos] = i;
            pos++;
        }
    }
    if (t == 127) g_cnt[j] = (sc[127] < MAXNZ) ? sc[127] : MAXNZ;
}

// ---------------- kernel 4: per-column sparse attention + softmax + output ------
// one block per column j, warp b handles batch b.
__global__ __launch_bounds__(128) void col_k(float* __restrict__ out,
                                             float* __restrict__ attn,
                                             int write_attn) {
    const int j    = blockIdx.x;
    const int warp = threadIdx.x >> 5;   // = batch
    const int lane = threadIdx.x & 31;

    __shared__ float s_ai[U_];
    __shared__ float s_p[B_][MAXNZ];
    __shared__ int   s_rows[MAXNZ];

    const int nnz = g_cnt[j];
    s_ai[threadIdx.x] = g_aiT[(size_t)j * U_ + threadIdx.x];
    for (int e = threadIdx.x; e < nnz; e += 128)
        s_rows[e] = g_rows[(size_t)j * MAXNZ + e];
    __syncthreads();

    const float* fb = g_f + (size_t)warp * N_ * U_;
    float fj[4], aiv[4];
#pragma unroll
    for (int q = 0; q < 4; q++) {
        int u = lane + 32 * q;
        fj[q]  = fb[(size_t)j * U_ + u];
        aiv[q] = s_ai[u];
    }

    // logits: val = f[b,i,:].ai[:,j] + f[b,j,:].aj[:,i]  (+1e9 if mask==2)
    for (int e = 0; e < nnz; e++) {
        int enc = s_rows[e];
        int i = enc & 0xFFFF;
        const float* fi  = fb + (size_t)i * U_;
        const float* ajr = g_ajT + (size_t)i * U_;
        float acc = 0.0f;
#pragma unroll
        for (int q = 0; q < 4; q++) {
            int u = lane + 32 * q;
            acc = fmaf(fi[u], aiv[q], acc);
            acc = fmaf(fj[q], ajr[u], acc);
        }
#pragma unroll
        for (int off = 16; off; off >>= 1)
            acc += __shfl_xor_sync(0xFFFFFFFFu, acc, off);
        if (lane == 0)
            s_p[warp][e] = acc + ((enc & 0x10000) ? 1.0e9f : 0.0f);
    }
    __syncwarp();

    // softmax over the nnz entries (all other column entries underflow to 0)
    float mx = -3.0e38f;
    for (int e = lane; e < nnz; e += 32) mx = fmaxf(mx, s_p[warp][e]);
#pragma unroll
    for (int off = 16; off; off >>= 1)
        mx = fmaxf(mx, __shfl_xor_sync(0xFFFFFFFFu, mx, off));
    float ssum = 0.0f;
    for (int e = lane; e < nnz; e += 32) {
        float p = expf(s_p[warp][e] - mx);
        s_p[warp][e] = p;
        ssum += p;
    }
#pragma unroll
    for (int off = 16; off; off >>= 1)
        ssum += __shfl_xor_sync(0xFFFFFFFFu, ssum, off);
    const float inv = 1.0f / ssum;

    // scatter attn nonzeros
    if (write_attn) {
        for (int e = lane; e < nnz; e += 32) {
            int i = s_rows[e] & 0xFFFF;
            attn[((size_t)warp * N_ + i) * N_ + j] = s_p[warp][e] * inv;
        }
    }
    __syncwarp();

    // out[b,j,:] = relu( sum_e p_e * f[b,i_e,:] )
    float acc_o[4] = {0.f, 0.f, 0.f, 0.f};
    for (int e = 0; e < nnz; e++) {
        int i = s_rows[e] & 0xFFFF;
        float p = s_p[warp][e] * inv;
        const float* fi = fb + (size_t)i * U_;
#pragma unroll
        for (int q = 0; q < 4; q++)
            acc_o[q] = fmaf(p, fi[lane + 32 * q], acc_o[q]);
    }
#pragma unroll
    for (int q = 0; q < 4; q++) {
        float v = acc_o[q];
        out[((size_t)warp * N_ + j) * U_ + lane + 32 * q] = (v > 0.0f) ? v : 0.0f;
    }
}

// ---------------- launch ----------------
extern "C" void kernel_launch(void* const* d_in, const int* in_sizes, int n_in,
                              void* d_out, int out_size) {
    const float* inputs = (const float*)d_in[0];   // [B,N,F]
    const float* w      = (const float*)d_in[1];   // [F,U]
    const float* ai     = (const float*)d_in[2];   // [U,N]
    const float* aj     = (const float*)d_in[3];   // [U,N]
    const float* adj    = (const float*)d_in[4];   // [N,N]

    const size_t OUT1 = (size_t)B_ * N_ * U_;           // 2,097,152
    const size_t ATTN = (size_t)B_ * N_ * N_;           // 67,108,864
    float* out_relu = (float*)d_out;
    float* attn = nullptr;
    if ((size_t)out_size >= OUT1 + ATTN) attn = (float*)d_out + OUT1;

    if (attn) cudaMemsetAsync(attn, 0, ATTN * sizeof(float), 0);

    transpose_k<<<dim3(N_ / 32, U_ / 32, 2), dim3(32, 8)>>>(ai, aj);
    gemm_f<<<M_ / 128, 256>>>(inputs, w);
    build_k<<<N_, 128>>>(adj);
    col_k<<<N_, 128>>>(out_relu, attn, attn != nullptr);
}